// round 2
// baseline (speedup 1.0000x reference)
#include <cuda_runtime.h>
#include <math.h>

// features: (B=16, C=256, H=64, W=64) fp32
// out:      (B, H, W) fp32
//
// Thread mapping: each warp owns 8 "pixel groups" (4 adjacent w-pixels each).
// lane = g_local*4 + q : g_local in [0,8) selects group, q in [0,4) selects
// the channel quarter (64 channels) this lane reduces. float4 loads; the 8
// lanes sharing q read one contiguous 128B line per channel -> fully coalesced.
// Partial (sum, sumsq) per pixel combined across q by shfl_xor butterfly.
// Lane then finishes pixel (group*4 + q): out index == global thread id.

#define C_DIM   256
#define HW      4096
#define NPIX    65536
#define TPB     256

__global__ void __launch_bounds__(TPB, 8)
fis_kernel(const float4* __restrict__ f4,
           const float* __restrict__ W1,   // (3,16)
           const float* __restrict__ b1,   // 16
           const float* __restrict__ W2,   // (16,1)
           const float* __restrict__ b2,   // 1
           float* __restrict__ out)
{
    __shared__ float sp[81];  // [0:48) W1, [48:64) b1, [64:80) W2, [80] b2
    int tid = threadIdx.x;
    if (tid < 81) {
        float v;
        if (tid < 48)      v = W1[tid];
        else if (tid < 64) v = b1[tid - 48];
        else if (tid < 80) v = W2[tid - 64];
        else               v = b2[0];
        sp[tid] = v;
    }
    __syncthreads();

    int t      = blockIdx.x * TPB + tid;       // global thread id == out pixel id
    int lane   = tid & 31;
    int q      = lane & 3;                      // channel quarter
    int warp_g = (t >> 5);                      // global warp id
    int group  = warp_g * 8 + (lane >> 2);      // pixel-group id in [0, 16384)

    int b   = group >> 10;                      // 1024 groups per image
    int hw4 = group & 1023;                     // float4 index within HW plane

    // float4 view: each image plane row of HW floats = 1024 float4s
    const float4* __restrict__ src =
        f4 + (size_t)b * C_DIM * 1024 + (size_t)(q * 64) * 1024 + hw4;

    float4 s  = make_float4(0.f, 0.f, 0.f, 0.f);
    float4 ss = make_float4(0.f, 0.f, 0.f, 0.f);

    #pragma unroll 8
    for (int c = 0; c < 64; ++c) {
        float4 v = __ldg(src + (size_t)c * 1024);
        s.x += v.x;  s.y += v.y;  s.z += v.z;  s.w += v.w;
        ss.x = fmaf(v.x, v.x, ss.x);
        ss.y = fmaf(v.y, v.y, ss.y);
        ss.z = fmaf(v.z, v.z, ss.z);
        ss.w = fmaf(v.w, v.w, ss.w);
    }

    // Combine the 4 channel-quarters (lane bits 0,1) via butterfly.
    const unsigned FULL = 0xFFFFFFFFu;
    #pragma unroll
    for (int m = 1; m <= 2; m <<= 1) {
        s.x  += __shfl_xor_sync(FULL, s.x,  m);
        s.y  += __shfl_xor_sync(FULL, s.y,  m);
        s.z  += __shfl_xor_sync(FULL, s.z,  m);
        s.w  += __shfl_xor_sync(FULL, s.w,  m);
        ss.x += __shfl_xor_sync(FULL, ss.x, m);
        ss.y += __shfl_xor_sync(FULL, ss.y, m);
        ss.z += __shfl_xor_sync(FULL, ss.z, m);
        ss.w += __shfl_xor_sync(FULL, ss.w, m);
    }

    // This lane finishes pixel (group*4 + q): pick component q.
    float sv  = (q == 0) ? s.x  : (q == 1) ? s.y  : (q == 2) ? s.z  : s.w;
    float ssv = (q == 0) ? ss.x : (q == 1) ? ss.y : (q == 2) ? ss.z : ss.w;

    const float inv_c  = 1.0f / 256.0f;
    const float inv_c1 = 1.0f / 255.0f;
    float mag = sqrtf(ssv * inv_c);
    float var = (ssv - sv * sv * inv_c) * inv_c1;
    var = fmaxf(var, 0.0f);
    float sd  = sqrtf(var);

    float x0 = fminf(mag, 1.0f);
    float x1 = fminf(var, 1.0f);
    float x2 = fminf(sd,  1.0f);

    float acc = sp[80];
    #pragma unroll
    for (int o = 0; o < 16; ++o) {
        float h = sp[48 + o];
        h = fmaf(x0, sp[o],      h);
        h = fmaf(x1, sp[16 + o], h);
        h = fmaf(x2, sp[32 + o], h);
        h = fmaxf(h, 0.0f);
        acc = fmaf(h, sp[64 + o], acc);
    }
    out[t] = 1.0f / (1.0f + __expf(-acc));   // out index == t (coalesced)
}

extern "C" void kernel_launch(void* const* d_in, const int* in_sizes, int n_in,
                              void* d_out, int out_size)
{
    const float4* f4 = (const float4*)d_in[0];
    const float*  W1 = (const float*)d_in[1];
    const float*  b1 = (const float*)d_in[2];
    const float*  W2 = (const float*)d_in[3];
    const float*  b2 = (const float*)d_in[4];
    float* out = (float*)d_out;

    fis_kernel<<<NPIX / TPB, TPB>>>(f4, W1, b1, W2, b2, out);
}